// round 9
// baseline (speedup 1.0000x reference)
#include <cuda_runtime.h>
#include <cuda_bf16.h>

// Problem constants
#define Bn   4
#define Sn   512
#define Jn   24
#define Hn   128
#define NHn  8
#define HSn  16
#define HSP  20          // padded row stride for Q/K/V in smem (float4-aligned, conflict-free)
#define LN_EPS 1e-5f

// Scratch: attention head outputs in (B, S, J, NH*HS) layout (same flat layout as x/out)
__device__ float g_heads[Bn * Sn * Jn * Hn];

// ---------------------------------------------------------------------------
// Kernel 1: per (b, n, j) block — QKV projection + causal softmax attention
//   grid = B*NH*J = 768 blocks, 512 threads, dyn smem = 3*S*HSP + 10240 floats
// ---------------------------------------------------------------------------
__global__ void __launch_bounds__(512, 1)
attn_kernel(const float* __restrict__ x,
            const float* __restrict__ qm,
            const float* __restrict__ km,
            const float* __restrict__ vm)
{
    extern __shared__ float sm[];
    float* Q  = sm;                    // Sn * HSP
    float* K  = Q + Sn * HSP;          // Sn * HSP
    float* V  = K + Sn * HSP;          // Sn * HSP
    float* Wbuf = V + Sn * HSP;        // 10240 floats: weights + X tile, later score buffer
    float* Wq = Wbuf;                  // Hn*HSn = 2048
    float* Wk = Wq + Hn * HSn;
    float* Wv = Wk + Hn * HSn;
    float* Xt = Wv + Hn * HSn;         // 32 * Hn = 4096

    const int tid = threadIdx.x;
    const int blk = blockIdx.x;
    const int j = blk % Jn;
    const int n = (blk / Jn) % NHn;
    const int b = blk / (Jn * NHn);

    // --- load per-(n,j) projection weights (H x HS each) ---
    const float* qmj = qm + ((n * Jn + j) * Hn) * HSn;
    const float* kmj = km + ((n * Jn + j) * Hn) * HSn;
    const float* vmj = vm + ((n * Jn + j) * Hn) * HSn;
    for (int i = tid; i < Hn * HSn; i += 512) {
        Wq[i] = qmj[i];
        Wk[i] = kmj[i];
        Wv[i] = vmj[i];
    }
    __syncthreads();

    // --- QKV projection in 16 tiles of 32 sequence rows ---
    const int pr = tid >> 4;     // 0..31 : row within tile
    const int pd = tid & 15;     // 0..15 : head dim
    for (int t0 = 0; t0 < Sn; t0 += 32) {
        for (int i = tid; i < 32 * Hn; i += 512) {
            int rr = i >> 7, h = i & 127;
            Xt[i] = x[(((b * Sn) + (t0 + rr)) * Jn + j) * Hn + h];
        }
        __syncthreads();
        float aq = 0.f, ak = 0.f, av = 0.f;
        #pragma unroll 8
        for (int h = 0; h < Hn; ++h) {
            float xv = Xt[pr * Hn + h];
            aq = fmaf(xv, Wq[h * HSn + pd], aq);
            ak = fmaf(xv, Wk[h * HSn + pd], ak);
            av = fmaf(xv, Wv[h * HSn + pd], av);
        }
        int s = t0 + pr;
        Q[s * HSP + pd] = aq;
        K[s * HSP + pd] = ak;
        V[s * HSP + pd] = av;
        __syncthreads();
    }

    // --- causal attention: one warp per query row, rows strided by 16 warps ---
    // score buffer reuses the weight/X-tile region: 16 warps * 512 floats = 8192 <= 10240
    float* SC = Wbuf;
    const int warp = tid >> 5;
    const int lane = tid & 31;
    float* sc = SC + warp * Sn;

    float* gout = g_heads + ((b * Sn) * Jn + j) * Hn + n * HSn;

    for (int s = warp; s < Sn; s += 16) {
        const float4 q0 = *(const float4*)(Q + s * HSP + 0);
        const float4 q1 = *(const float4*)(Q + s * HSP + 4);
        const float4 q2 = *(const float4*)(Q + s * HSP + 8);
        const float4 q3 = *(const float4*)(Q + s * HSP + 12);

        // pass 1: scores (scaled by 1/sqrt(HS)=0.25) + row max
        float mx = -1e30f;
        for (int t = lane; t <= s; t += 32) {
            const float4 k0 = *(const float4*)(K + t * HSP + 0);
            const float4 k1 = *(const float4*)(K + t * HSP + 4);
            const float4 k2 = *(const float4*)(K + t * HSP + 8);
            const float4 k3 = *(const float4*)(K + t * HSP + 12);
            float acc;
            acc = q0.x * k0.x;
            acc = fmaf(q0.y, k0.y, acc);
            acc = fmaf(q0.z, k0.z, acc);
            acc = fmaf(q0.w, k0.w, acc);
            acc = fmaf(q1.x, k1.x, acc);
            acc = fmaf(q1.y, k1.y, acc);
            acc = fmaf(q1.z, k1.z, acc);
            acc = fmaf(q1.w, k1.w, acc);
            acc = fmaf(q2.x, k2.x, acc);
            acc = fmaf(q2.y, k2.y, acc);
            acc = fmaf(q2.z, k2.z, acc);
            acc = fmaf(q2.w, k2.w, acc);
            acc = fmaf(q3.x, k3.x, acc);
            acc = fmaf(q3.y, k3.y, acc);
            acc = fmaf(q3.z, k3.z, acc);
            acc = fmaf(q3.w, k3.w, acc);
            acc *= 0.25f;
            sc[t] = acc;
            mx = fmaxf(mx, acc);
        }
        #pragma unroll
        for (int o = 16; o; o >>= 1)
            mx = fmaxf(mx, __shfl_xor_sync(0xffffffffu, mx, o));

        // pass 2: exp + weighted V accumulate
        float sum = 0.f;
        float oacc[HSn];
        #pragma unroll
        for (int dd = 0; dd < HSn; ++dd) oacc[dd] = 0.f;
        for (int t = lane; t <= s; t += 32) {
            float e = __expf(sc[t] - mx);
            sum += e;
            const float4 v0 = *(const float4*)(V + t * HSP + 0);
            const float4 v1 = *(const float4*)(V + t * HSP + 4);
            const float4 v2 = *(const float4*)(V + t * HSP + 8);
            const float4 v3 = *(const float4*)(V + t * HSP + 12);
            oacc[0]  = fmaf(e, v0.x, oacc[0]);
            oacc[1]  = fmaf(e, v0.y, oacc[1]);
            oacc[2]  = fmaf(e, v0.z, oacc[2]);
            oacc[3]  = fmaf(e, v0.w, oacc[3]);
            oacc[4]  = fmaf(e, v1.x, oacc[4]);
            oacc[5]  = fmaf(e, v1.y, oacc[5]);
            oacc[6]  = fmaf(e, v1.z, oacc[6]);
            oacc[7]  = fmaf(e, v1.w, oacc[7]);
            oacc[8]  = fmaf(e, v2.x, oacc[8]);
            oacc[9]  = fmaf(e, v2.y, oacc[9]);
            oacc[10] = fmaf(e, v2.z, oacc[10]);
            oacc[11] = fmaf(e, v2.w, oacc[11]);
            oacc[12] = fmaf(e, v3.x, oacc[12]);
            oacc[13] = fmaf(e, v3.y, oacc[13]);
            oacc[14] = fmaf(e, v3.z, oacc[14]);
            oacc[15] = fmaf(e, v3.w, oacc[15]);
        }
        #pragma unroll
        for (int o = 16; o; o >>= 1) {
            sum += __shfl_xor_sync(0xffffffffu, sum, o);
            #pragma unroll
            for (int dd = 0; dd < HSn; ++dd)
                oacc[dd] += __shfl_xor_sync(0xffffffffu, oacc[dd], o);
        }
        float inv = 1.f / sum;
        float myval = 0.f;
        #pragma unroll
        for (int dd = 0; dd < HSn; ++dd)
            if (lane == dd) myval = oacc[dd];
        if (lane < HSn)
            gout[s * (Jn * Hn) + lane] = myval * inv;
    }
}

// ---------------------------------------------------------------------------
// Kernel 2: per (j, 64-row tile) — output projection (O @ P[j]) + residual + LN
//   grid = J * (B*S/64) = 24*32 = 768 blocks, 256 threads
//   dyn smem = P (128x128) + O tile (64x128) + Y tile (64x128) = 128KB
// ---------------------------------------------------------------------------
__global__ void __launch_bounds__(256, 1)
proj_ln_kernel(const float* __restrict__ x,
               const float* __restrict__ proj,
               const float* __restrict__ gamma,
               const float* __restrict__ beta,
               float* __restrict__ out)
{
    extern __shared__ float sm2[];
    float* P = sm2;                 // Hn*Hn = 16384
    float* O = P + Hn * Hn;         // 64*Hn = 8192
    float* Y = O + 64 * Hn;         // 64*Hn = 8192

    const int tid  = threadIdx.x;
    const int j    = blockIdx.x >> 5;   // 32 tiles per joint
    const int tile = blockIdx.x & 31;
    const int m0   = tile * 64;         // flat row base in (b*S + s)

    const float* Pj = proj + j * Hn * Hn;
    for (int i = tid; i < Hn * Hn; i += 256) P[i] = Pj[i];
    for (int i = tid; i < 64 * Hn; i += 256) {
        int rr = i >> 7, h = i & 127;
        O[i] = g_heads[((m0 + rr) * Jn + j) * Hn + h];
    }
    __syncthreads();

    // GEMM: each thread computes 8 rows x 4 cols
    const int ty = tid >> 5;   // 0..7 -> rows ty*8 .. ty*8+7
    const int tx = tid & 31;   // 0..31 -> cols tx*4 .. tx*4+3
    float acc[8][4];
    #pragma unroll
    for (int i = 0; i < 8; ++i)
        #pragma unroll
        for (int c = 0; c < 4; ++c) acc[i][c] = 0.f;

    #pragma unroll 4
    for (int h = 0; h < Hn; ++h) {
        float4 p = *(const float4*)(P + h * Hn + tx * 4);
        #pragma unroll
        for (int i = 0; i < 8; ++i) {
            float ov = O[(ty * 8 + i) * Hn + h];
            acc[i][0] = fmaf(ov, p.x, acc[i][0]);
            acc[i][1] = fmaf(ov, p.y, acc[i][1]);
            acc[i][2] = fmaf(ov, p.z, acc[i][2]);
            acc[i][3] = fmaf(ov, p.w, acc[i][3]);
        }
    }
    #pragma unroll
    for (int i = 0; i < 8; ++i)
        *(float4*)(Y + (ty * 8 + i) * Hn + tx * 4) =
            make_float4(acc[i][0], acc[i][1], acc[i][2], acc[i][3]);
    __syncthreads();

    // residual + LayerNorm: one warp per row, 8 rows per warp
    const int warp = ty;
    const int lane = tx;
    const float4 g  = *(const float4*)(gamma + lane * 4);
    const float4 bt = *(const float4*)(beta  + lane * 4);
    for (int rr = warp; rr < 64; rr += 8) {
        const int m = m0 + rr;
        const float* xrow = x + (m * Jn + j) * Hn;
        float4 xv = *(const float4*)(xrow + lane * 4);
        float4 yv = *(const float4*)(Y + rr * Hn + lane * 4);
        float v0 = yv.x + xv.x;
        float v1 = yv.y + xv.y;
        float v2 = yv.z + xv.z;
        float v3 = yv.w + xv.w;
        float ssum = v0 + v1 + v2 + v3;
        float ssq  = fmaf(v0, v0, fmaf(v1, v1, fmaf(v2, v2, v3 * v3)));
        #pragma unroll
        for (int o = 16; o; o >>= 1) {
            ssum += __shfl_xor_sync(0xffffffffu, ssum, o);
            ssq  += __shfl_xor_sync(0xffffffffu, ssq, o);
        }
        float mean = ssum * (1.f / 128.f);
        float var  = ssq * (1.f / 128.f) - mean * mean;
        float rstd = rsqrtf(var + LN_EPS);
        float4 res;
        res.x = (v0 - mean) * rstd * g.x + bt.x;
        res.y = (v1 - mean) * rstd * g.y + bt.y;
        res.z = (v2 - mean) * rstd * g.z + bt.z;
        res.w = (v3 - mean) * rstd * g.w + bt.w;
        *(float4*)(out + (m * Jn + j) * Hn + lane * 4) = res;
    }
}

// ---------------------------------------------------------------------------
// Launch
// ---------------------------------------------------------------------------
extern "C" void kernel_launch(void* const* d_in, const int* in_sizes, int n_in,
                              void* d_out, int out_size)
{
    const float* x     = (const float*)d_in[0];
    // d_in[1] = mask (pure causal, derived analytically — unused)
    const float* qm    = (const float*)d_in[2];
    const float* km    = (const float*)d_in[3];
    const float* vm    = (const float*)d_in[4];
    const float* proj  = (const float*)d_in[5];
    const float* gamma = (const float*)d_in[6];
    const float* beta  = (const float*)d_in[7];
    float* out = (float*)d_out;

    const int smem1 = (3 * Sn * HSP + 3 * Hn * HSn + 32 * Hn) * (int)sizeof(float); // 163840
    const int smem2 = (Hn * Hn + 2 * 64 * Hn) * (int)sizeof(float);                 // 131072

    cudaFuncSetAttribute(attn_kernel, cudaFuncAttributeMaxDynamicSharedMemorySize, smem1);
    cudaFuncSetAttribute(proj_ln_kernel, cudaFuncAttributeMaxDynamicSharedMemorySize, smem2);

    attn_kernel<<<Bn * NHn * Jn, 512, smem1>>>(x, qm, km, vm);
    proj_ln_kernel<<<Jn * (Bn * Sn / 64), 256, smem2>>>(x, proj, gamma, beta, out);
}

// round 10
// speedup vs baseline: 1.5629x; 1.5629x over previous
#include <cuda_runtime.h>
#include <cuda_bf16.h>

// Problem constants
#define Bn   4
#define Sn   512
#define Jn   24
#define Hn   128
#define NHn  8
#define HSn  16
#define HSP  18          // Q/K/V smem row stride: even (8B align) + conflict-free LDS.64
#define WP   130         // transposed-weight row stride (bank-conflict-free per pd)
#define OTP  130         // transposed-O row stride in kernel 2
#define LN_EPS 1e-5f

typedef unsigned long long u64;

// Scratch: attention head outputs in (B, S, J, NH*HS) layout
__device__ float g_heads[Bn * Sn * Jn * Hn];

// ---- packed f32x2 helpers ----
__device__ __forceinline__ u64 f2pack(float lo, float hi) {
    u64 r; asm("mov.b64 %0,{%1,%2};" : "=l"(r) : "f"(lo), "f"(hi)); return r;
}
__device__ __forceinline__ void f2unpack(u64 v, float& lo, float& hi) {
    asm("mov.b64 {%0,%1},%2;" : "=f"(lo), "=f"(hi) : "l"(v));
}
__device__ __forceinline__ u64 fma2(u64 a, u64 b, u64 c) {
    u64 d; asm("fma.rn.f32x2 %0,%1,%2,%3;" : "=l"(d) : "l"(a), "l"(b), "l"(c)); return d;
}
__device__ __forceinline__ u64 mul2(u64 a, u64 b) {
    u64 d; asm("mul.rn.f32x2 %0,%1,%2;" : "=l"(d) : "l"(a), "l"(b)); return d;
}
__device__ __forceinline__ u64 add2(u64 a, u64 b) {
    u64 d; asm("add.rn.f32x2 %0,%1,%2;" : "=l"(d) : "l"(a), "l"(b)); return d;
}
__device__ __forceinline__ float f2sum(u64 v) { float a, b; f2unpack(v, a, b); return a + b; }
__device__ __forceinline__ u64 lds2(const float* p) { return *reinterpret_cast<const u64*>(p); }

// ---------------------------------------------------------------------------
// Kernel 1: per (b, n, j) block — QKV projection + causal single-pass attention
//   grid = B*NH*J = 768 blocks, 256 threads
// ---------------------------------------------------------------------------
__global__ void __launch_bounds__(256, 1)
attn_kernel(const float* __restrict__ x,
            const float* __restrict__ qm,
            const float* __restrict__ km,
            const float* __restrict__ vm)
{
    extern __shared__ float sm[];
    float* Q   = sm;                    // Sn * HSP = 9216
    float* K   = Q + Sn * HSP;
    float* V   = K + Sn * HSP;
    float* Wqt = V + Sn * HSP;          // 16 * WP
    float* Wkt = Wqt + HSn * WP;
    float* Wvt = Wkt + HSn * WP;
    float* Xt  = Wvt + HSn * WP;        // 64 * 128

    const int tid = threadIdx.x;
    const int blk = blockIdx.x;
    const int j = blk % Jn;
    const int n = (blk / Jn) % NHn;
    const int b = blk / (Jn * NHn);

    // --- Phase A: load weights transposed to [pd][h] (h contiguous) ---
    const float* qmj = qm + ((n * Jn + j) * Hn) * HSn;
    const float* kmj = km + ((n * Jn + j) * Hn) * HSn;
    const float* vmj = vm + ((n * Jn + j) * Hn) * HSn;
    for (int i = tid; i < Hn * HSn; i += 256) {
        int h = i >> 4, pd_ = i & 15;
        Wqt[pd_ * WP + h] = qmj[i];
        Wkt[pd_ * WP + h] = kmj[i];
        Wvt[pd_ * WP + h] = vmj[i];
    }
    __syncthreads();

    // --- Phase B: QKV projection, 8 tiles of 64 rows, 4 rows per thread ---
    const int pr = tid >> 4;     // 0..15
    const int pd = tid & 15;     // 0..15
    const float* wq = Wqt + pd * WP;
    const float* wk = Wkt + pd * WP;
    const float* wv = Wvt + pd * WP;

    for (int t0 = 0; t0 < Sn; t0 += 64) {
        for (int i = tid; i < 64 * Hn; i += 256) {
            int rr = i >> 7, h = i & 127;
            Xt[i] = x[(((size_t)b * Sn + (t0 + rr)) * Jn + j) * Hn + h];
        }
        __syncthreads();

        u64 aq[4] = {0,0,0,0}, ak[4] = {0,0,0,0}, av[4] = {0,0,0,0};
        #pragma unroll 8
        for (int h = 0; h < Hn; h += 2) {
            u64 wqv = lds2(wq + h);
            u64 wkv = lds2(wk + h);
            u64 wvv = lds2(wv + h);
            #pragma unroll
            for (int k = 0; k < 4; ++k) {
                u64 xv = lds2(Xt + (pr + 16 * k) * Hn + h);
                aq[k] = fma2(xv, wqv, aq[k]);
                ak[k] = fma2(xv, wkv, ak[k]);
                av[k] = fma2(xv, wvv, av[k]);
            }
        }
        #pragma unroll
        for (int k = 0; k < 4; ++k) {
            int s = t0 + pr + 16 * k;
            Q[s * HSP + pd] = f2sum(aq[k]);
            K[s * HSP + pd] = f2sum(ak[k]);
            V[s * HSP + pd] = f2sum(av[k]);
        }
        __syncthreads();
    }

    // --- Phase C: single-pass causal attention, QB=4 queries per warp ---
    const int warp = tid >> 5;
    const int lane = tid & 31;
    const u64 quarter = f2pack(0.25f, 0.25f);

    for (int g = warp; g < Sn / 4; g += 8) {
        const int s0 = g * 4;

        // load + pre-scale 4 query rows (fold 1/sqrt(HS)=0.25 into q)
        u64 qr[4][8];
        #pragma unroll
        for (int q = 0; q < 4; ++q) {
            const float* qp = Q + (s0 + q) * HSP;
            #pragma unroll
            for (int i = 0; i < 8; ++i)
                qr[q][i] = mul2(lds2(qp + 2 * i), quarter);
        }

        u64 oacc[4][8];
        #pragma unroll
        for (int q = 0; q < 4; ++q)
            #pragma unroll
            for (int i = 0; i < 8; ++i) oacc[q][i] = 0ull;
        float sum0 = 0.f, sum1 = 0.f, sum2 = 0.f, sum3 = 0.f;

        for (int t = lane; t < s0 + 4; t += 32) {
            const float* kp = K + t * HSP;
            u64 kk[8];
            #pragma unroll
            for (int i = 0; i < 8; ++i) kk[i] = lds2(kp + 2 * i);

            float e[4];
            #pragma unroll
            for (int q = 0; q < 4; ++q) {
                u64 d = mul2(qr[q][0], kk[0]);
                #pragma unroll
                for (int i = 1; i < 8; ++i) d = fma2(qr[q][i], kk[i], d);
                float ev = __expf(f2sum(d));
                e[q] = (t <= s0 + q) ? ev : 0.f;
            }
            sum0 += e[0]; sum1 += e[1]; sum2 += e[2]; sum3 += e[3];

            const float* vp = V + t * HSP;
            u64 vv[8];
            #pragma unroll
            for (int i = 0; i < 8; ++i) vv[i] = lds2(vp + 2 * i);
            #pragma unroll
            for (int q = 0; q < 4; ++q) {
                u64 eq = f2pack(e[q], e[q]);
                #pragma unroll
                for (int i = 0; i < 8; ++i)
                    oacc[q][i] = fma2(eq, vv[i], oacc[q][i]);
            }
        }

        // warp reduction (packed sums + packed V accumulators)
        u64 s01 = f2pack(sum0, sum1), s23 = f2pack(sum2, sum3);
        #pragma unroll
        for (int o = 16; o; o >>= 1) {
            s01 = add2(s01, __shfl_xor_sync(0xffffffffu, s01, o));
            s23 = add2(s23, __shfl_xor_sync(0xffffffffu, s23, o));
            #pragma unroll
            for (int q = 0; q < 4; ++q)
                #pragma unroll
                for (int i = 0; i < 8; ++i)
                    oacc[q][i] = add2(oacc[q][i], __shfl_xor_sync(0xffffffffu, oacc[q][i], o));
        }
        float fs0, fs1, fs2, fs3;
        f2unpack(s01, fs0, fs1); f2unpack(s23, fs2, fs3);
        float inv[4] = {1.f / fs0, 1.f / fs1, 1.f / fs2, 1.f / fs3};

        // lanes 0..15 each write one float4 chunk (query q, chunk c)
        #pragma unroll
        for (int q = 0; q < 4; ++q) {
            #pragma unroll
            for (int c = 0; c < 4; ++c) {
                if (lane == q * 4 + c) {
                    float x0, x1, x2, x3;
                    f2unpack(oacc[q][2 * c],     x0, x1);
                    f2unpack(oacc[q][2 * c + 1], x2, x3);
                    float4 r = make_float4(x0 * inv[q], x1 * inv[q],
                                           x2 * inv[q], x3 * inv[q]);
                    *(float4*)(g_heads + (((size_t)b * Sn + (s0 + q)) * Jn + j) * Hn
                               + n * HSn + c * 4) = r;
                }
            }
        }
    }
}

// ---------------------------------------------------------------------------
// Kernel 2: per (j, 128-row tile) — output projection + residual + LayerNorm
//   grid = J * (B*S/128) = 384 blocks, 256 threads
// ---------------------------------------------------------------------------
__global__ void __launch_bounds__(256, 1)
proj_ln_kernel(const float* __restrict__ x,
               const float* __restrict__ proj,
               const float* __restrict__ gamma,
               const float* __restrict__ beta,
               float* __restrict__ out)
{
    extern __shared__ float sm2[];
    float* P  = sm2;                 // Hn*Hn = 16384
    float* Ot = P + Hn * Hn;         // 128 * OTP (transposed O: [h][row])

    const int tid  = threadIdx.x;
    const int j    = blockIdx.x >> 4;
    const int tile = blockIdx.x & 15;
    const int m0   = tile * 128;

    const float* Pj = proj + j * Hn * Hn;
    for (int i = tid; i < Hn * Hn; i += 256) P[i] = Pj[i];
    for (int i = tid; i < 128 * Hn; i += 256) {
        int rr = i >> 7, h = i & 127;
        Ot[h * OTP + rr] = g_heads[((size_t)(m0 + rr) * Jn + j) * Hn + h];
    }
    __syncthreads();

    const int ty   = tid >> 5;          // warp: rows ty*16 .. ty*16+15
    const int lane = tid & 31;          // cols lane*4 .. lane*4+3
    const int rowbase = ty * 16;

    // acc[r][c] packs {row 2r, row 2r+1} for column lane*4+c
    u64 acc[8][4];
    #pragma unroll
    for (int r = 0; r < 8; ++r)
        #pragma unroll
        for (int c = 0; c < 4; ++c) acc[r][c] = 0ull;

    const float* obase = Ot + rowbase;
    #pragma unroll 2
    for (int h = 0; h < Hn; ++h) {
        float4 p = *(const float4*)(P + h * Hn + lane * 4);
        u64 d0 = f2pack(p.x, p.x);
        u64 d1 = f2pack(p.y, p.y);
        u64 d2 = f2pack(p.z, p.z);
        u64 d3 = f2pack(p.w, p.w);
        const float* oc = obase + h * OTP;
        #pragma unroll
        for (int r = 0; r < 8; ++r) {
            u64 ov = lds2(oc + 2 * r);
            acc[r][0] = fma2(ov, d0, acc[r][0]);
            acc[r][1] = fma2(ov, d1, acc[r][1]);
            acc[r][2] = fma2(ov, d2, acc[r][2]);
            acc[r][3] = fma2(ov, d3, acc[r][3]);
        }
    }

    // residual + LayerNorm, two rows (even/odd of pair) at a time
    const float4 g  = *(const float4*)(gamma + lane * 4);
    const float4 bt = *(const float4*)(beta  + lane * 4);
    #pragma unroll
    for (int r = 0; r < 8; ++r) {
        const int row0 = rowbase + 2 * r;
        const float* xr = x + ((size_t)(m0 + row0) * Jn + j) * Hn + lane * 4;
        float4 xa = *(const float4*)xr;
        float4 xb = *(const float4*)(xr + Jn * Hn);

        float ve0, vo0, ve1, vo1, ve2, vo2, ve3, vo3;
        f2unpack(acc[r][0], ve0, vo0);
        f2unpack(acc[r][1], ve1, vo1);
        f2unpack(acc[r][2], ve2, vo2);
        f2unpack(acc[r][3], ve3, vo3);
        ve0 += xa.x; ve1 += xa.y; ve2 += xa.z; ve3 += xa.w;
        vo0 += xb.x; vo1 += xb.y; vo2 += xb.z; vo3 += xb.w;

        u64 ss = f2pack(ve0 + ve1 + ve2 + ve3, vo0 + vo1 + vo2 + vo3);
        u64 sq = f2pack(fmaf(ve0, ve0, fmaf(ve1, ve1, fmaf(ve2, ve2, ve3 * ve3))),
                        fmaf(vo0, vo0, fmaf(vo1, vo1, fmaf(vo2, vo2, vo3 * vo3))));
        #pragma unroll
        for (int o = 16; o; o >>= 1) {
            ss = add2(ss, __shfl_xor_sync(0xffffffffu, ss, o));
            sq = add2(sq, __shfl_xor_sync(0xffffffffu, sq, o));
        }
        float se, so, qe, qo;
        f2unpack(ss, se, so);
        f2unpack(sq, qe, qo);
        float me = se * (1.f / 128.f), mo = so * (1.f / 128.f);
        float re = rsqrtf(qe * (1.f / 128.f) - me * me + LN_EPS);
        float ro = rsqrtf(qo * (1.f / 128.f) - mo * mo + LN_EPS);

        float* orow = out + ((size_t)(m0 + row0) * Jn + j) * Hn + lane * 4;
        float4 oa, ob;
        oa.x = (ve0 - me) * re * g.x + bt.x;
        oa.y = (ve1 - me) * re * g.y + bt.y;
        oa.z = (ve2 - me) * re * g.z + bt.z;
        oa.w = (ve3 - me) * re * g.w + bt.w;
        ob.x = (vo0 - mo) * ro * g.x + bt.x;
        ob.y = (vo1 - mo) * ro * g.y + bt.y;
        ob.z = (vo2 - mo) * ro * g.z + bt.z;
        ob.w = (vo3 - mo) * ro * g.w + bt.w;
        *(float4*)orow = oa;
        *(float4*)(orow + Jn * Hn) = ob;
    }
}

// ---------------------------------------------------------------------------
// Launch
// ---------------------------------------------------------------------------
extern "C" void kernel_launch(void* const* d_in, const int* in_sizes, int n_in,
                              void* d_out, int out_size)
{
    const float* x     = (const float*)d_in[0];
    // d_in[1] = mask (pure causal, handled analytically)
    const float* qm    = (const float*)d_in[2];
    const float* km    = (const float*)d_in[3];
    const float* vm    = (const float*)d_in[4];
    const float* proj  = (const float*)d_in[5];
    const float* gamma = (const float*)d_in[6];
    const float* beta  = (const float*)d_in[7];
    float* out = (float*)d_out;

    const int smem1 = (3 * Sn * HSP + 3 * HSn * WP + 64 * Hn) * (int)sizeof(float); // 168320
    const int smem2 = (Hn * Hn + 128 * OTP) * (int)sizeof(float);                   // 132096

    cudaFuncSetAttribute(attn_kernel, cudaFuncAttributeMaxDynamicSharedMemorySize, smem1);
    cudaFuncSetAttribute(proj_ln_kernel, cudaFuncAttributeMaxDynamicSharedMemorySize, smem2);

    attn_kernel<<<Bn * NHn * Jn, 256, smem1>>>(x, qm, km, vm);
    proj_ln_kernel<<<Jn * (Bn * Sn / 128), 256, smem2>>>(x, proj, gamma, beta, out);
}

// round 11
// speedup vs baseline: 2.6036x; 1.6659x over previous
#include <cuda_runtime.h>
#include <cuda_bf16.h>

// Problem constants
#define Bn   4
#define Sn   512
#define Jn   24
#define Hn   128
#define NHn  8
#define HSn  16
#define HSP  18          // Q/K/V smem row stride (8B aligned)
#define WP   130         // transposed-weight row stride (conflict-free per pd)
#define OTP  66          // transposed-O row stride in kernel 2 (64 rows + pad)
#define LN_EPS 1e-5f

typedef unsigned long long u64;

// Scratch: attention head outputs in (B, S, J, NH*HS) layout
__device__ float g_heads[Bn * Sn * Jn * Hn];

// ---- packed f32x2 helpers ----
__device__ __forceinline__ u64 f2pack(float lo, float hi) {
    u64 r; asm("mov.b64 %0,{%1,%2};" : "=l"(r) : "f"(lo), "f"(hi)); return r;
}
__device__ __forceinline__ void f2unpack(u64 v, float& lo, float& hi) {
    asm("mov.b64 {%0,%1},%2;" : "=f"(lo), "=f"(hi) : "l"(v));
}
__device__ __forceinline__ u64 fma2(u64 a, u64 b, u64 c) {
    u64 d; asm("fma.rn.f32x2 %0,%1,%2,%3;" : "=l"(d) : "l"(a), "l"(b), "l"(c)); return d;
}
__device__ __forceinline__ u64 mul2(u64 a, u64 b) {
    u64 d; asm("mul.rn.f32x2 %0,%1,%2;" : "=l"(d) : "l"(a), "l"(b)); return d;
}
__device__ __forceinline__ float f2sum(u64 v) { float a, b; f2unpack(v, a, b); return a + b; }
__device__ __forceinline__ u64 lds2(const float* p) { return *reinterpret_cast<const u64*>(p); }

// ---------------------------------------------------------------------------
// Kernel 1: per (b, n, j) block — QKV projection + causal attention
//   grid = B*NH*J = 768 blocks, 256 threads
// ---------------------------------------------------------------------------
__global__ void __launch_bounds__(256, 1)
attn_kernel(const float* __restrict__ x,
            const float* __restrict__ qm,
            const float* __restrict__ km,
            const float* __restrict__ vm)
{
    extern __shared__ float sm[];
    float* Q   = sm;                    // Sn * HSP = 9216
    float* K   = Q + Sn * HSP;
    float* V   = K + Sn * HSP;
    float* Wqt = V + Sn * HSP;          // 16 * WP each
    float* Wkt = Wqt + HSn * WP;
    float* Wvt = Wkt + HSn * WP;
    float* Xt  = Wvt + HSn * WP;        // 64 * 128

    const int tid = threadIdx.x;
    const int blk = blockIdx.x;
    const int j = blk % Jn;
    const int n = (blk / Jn) % NHn;
    const int b = blk / (Jn * NHn);

    // --- Phase A: load weights transposed to [pd][h]; fold 0.25 into Wq ---
    const float* qmj = qm + ((n * Jn + j) * Hn) * HSn;
    const float* kmj = km + ((n * Jn + j) * Hn) * HSn;
    const float* vmj = vm + ((n * Jn + j) * Hn) * HSn;
    for (int i = tid; i < Hn * HSn; i += 256) {
        int h = i >> 4, pd_ = i & 15;
        Wqt[pd_ * WP + h] = qmj[i] * 0.25f;   // 1/sqrt(HS)
        Wkt[pd_ * WP + h] = kmj[i];
        Wvt[pd_ * WP + h] = vmj[i];
    }
    __syncthreads();

    // --- Phase B: QKV projection, 8 tiles of 64 rows, 4 rows per thread ---
    const int pr = tid >> 4;     // 0..15
    const int pd = tid & 15;     // 0..15
    const float* wq = Wqt + pd * WP;
    const float* wk = Wkt + pd * WP;
    const float* wv = Wvt + pd * WP;

    for (int t0 = 0; t0 < Sn; t0 += 64) {
        for (int i = tid; i < 64 * 32; i += 256) {
            int rr = i >> 5, c = i & 31;
            ((float4*)Xt)[i] = ((const float4*)(x + (((size_t)b * Sn + (t0 + rr)) * Jn + j) * Hn))[c];
        }
        __syncthreads();

        u64 aq[4] = {0,0,0,0}, ak[4] = {0,0,0,0}, av[4] = {0,0,0,0};
        #pragma unroll 8
        for (int h = 0; h < Hn; h += 2) {
            u64 wqv = lds2(wq + h);
            u64 wkv = lds2(wk + h);
            u64 wvv = lds2(wv + h);
            #pragma unroll
            for (int k = 0; k < 4; ++k) {
                u64 xv = lds2(Xt + (pr + 16 * k) * Hn + h);
                aq[k] = fma2(xv, wqv, aq[k]);
                ak[k] = fma2(xv, wkv, ak[k]);
                av[k] = fma2(xv, wvv, av[k]);
            }
        }
        #pragma unroll
        for (int k = 0; k < 4; ++k) {
            int s = t0 + pr + 16 * k;
            Q[s * HSP + pd] = f2sum(aq[k]);
            K[s * HSP + pd] = f2sum(ak[k]);
            V[s * HSP + pd] = f2sum(av[k]);
        }
        __syncthreads();
    }

    // --- Phase C: causal attention, lane = query, keys broadcast ---
    // warp -> group map balances fma cycles across SMSPs (pairs sum to 7+4? ->
    // SMSP s hosts warps s and s+4 -> groups s and 7-s, equal totals).
    const int warp = tid >> 5;
    const int lane = tid & 31;
    const int g = (warp < 4) ? warp : (11 - warp);   // 0..7
    const int qa = 64 * g + lane;
    const int qb = qa + 32;

    u64 qra[8], qrb[8];
    {
        const float* qpa = Q + qa * HSP;
        const float* qpb = Q + qb * HSP;
        #pragma unroll
        for (int i = 0; i < 8; ++i) {
            qra[i] = lds2(qpa + 2 * i);
            qrb[i] = lds2(qpb + 2 * i);
        }
    }

    u64 oa[8], ob[8];
    #pragma unroll
    for (int i = 0; i < 8; ++i) { oa[i] = 0ull; ob[i] = 0ull; }
    float suma = 0.f, sumb = 0.f;

    const int tend1 = 64 * g + 32;

    for (int t = 0; t < tend1; ++t) {
        const float* kp = K + t * HSP;
        u64 kk[8];
        #pragma unroll
        for (int i = 0; i < 8; ++i) kk[i] = lds2(kp + 2 * i);

        u64 da = mul2(qra[0], kk[0]);
        u64 db = mul2(qrb[0], kk[0]);
        #pragma unroll
        for (int i = 1; i < 8; ++i) {
            da = fma2(qra[i], kk[i], da);
            db = fma2(qrb[i], kk[i], db);
        }
        float ea = __expf(f2sum(da));
        float eb = __expf(f2sum(db));
        if (t > qa) ea = 0.f;            // qb >= tend1-? qb >= 64g+32 > t always
        suma += ea; sumb += eb;

        const float* vp = V + t * HSP;
        u64 ea2 = f2pack(ea, ea), eb2 = f2pack(eb, eb);
        #pragma unroll
        for (int i = 0; i < 8; ++i) {
            u64 vv = lds2(vp + 2 * i);
            oa[i] = fma2(ea2, vv, oa[i]);
            ob[i] = fma2(eb2, vv, ob[i]);
        }
    }
    // tail: only the upper 32 queries are active
    for (int t = tend1; t < tend1 + 32; ++t) {
        const float* kp = K + t * HSP;
        u64 kk[8];
        #pragma unroll
        for (int i = 0; i < 8; ++i) kk[i] = lds2(kp + 2 * i);
        u64 db = mul2(qrb[0], kk[0]);
        #pragma unroll
        for (int i = 1; i < 8; ++i) db = fma2(qrb[i], kk[i], db);
        float eb = __expf(f2sum(db));
        if (t > qb) eb = 0.f;
        sumb += eb;
        const float* vp = V + t * HSP;
        u64 eb2 = f2pack(eb, eb);
        #pragma unroll
        for (int i = 0; i < 8; ++i)
            ob[i] = fma2(eb2, lds2(vp + 2 * i), ob[i]);
    }

    // write: each lane owns rows qa, qb fully (no reductions)
    {
        float inva = 1.f / suma, invb = 1.f / sumb;
        float* pa = g_heads + (((size_t)b * Sn + qa) * Jn + j) * Hn + n * HSn;
        float* pb = g_heads + (((size_t)b * Sn + qb) * Jn + j) * Hn + n * HSn;
        #pragma unroll
        for (int c = 0; c < 4; ++c) {
            float a0, a1, a2, a3;
            f2unpack(oa[2 * c],     a0, a1);
            f2unpack(oa[2 * c + 1], a2, a3);
            ((float4*)pa)[c] = make_float4(a0 * inva, a1 * inva, a2 * inva, a3 * inva);
            float b0, b1, b2, b3;
            f2unpack(ob[2 * c],     b0, b1);
            f2unpack(ob[2 * c + 1], b2, b3);
            ((float4*)pb)[c] = make_float4(b0 * invb, b1 * invb, b2 * invb, b3 * invb);
        }
    }
}

// ---------------------------------------------------------------------------
// Kernel 2: per (j, 64-row tile) — output projection + residual + LayerNorm
//   grid = J * (B*S/64) = 768 blocks, 256 threads, 2 CTAs/SM
// ---------------------------------------------------------------------------
__global__ void __launch_bounds__(256, 2)
proj_ln_kernel(const float* __restrict__ x,
               const float* __restrict__ proj,
               const float* __restrict__ gamma,
               const float* __restrict__ beta,
               float* __restrict__ out)
{
    extern __shared__ float sm2[];
    float* P  = sm2;                 // Hn*Hn = 16384
    float* Ot = P + Hn * Hn;         // Hn * OTP (transposed O: [h][row]), 64 rows

    const int tid  = threadIdx.x;
    const int j    = blockIdx.x >> 5;
    const int tile = blockIdx.x & 31;
    const int m0   = tile * 64;

    const float* Pj = proj + j * Hn * Hn;
    for (int i = tid; i < Hn * Hn / 4; i += 256)
        ((float4*)P)[i] = ((const float4*)Pj)[i];
    for (int i = tid; i < 64 * Hn; i += 256) {
        int rr = i >> 7, h = i & 127;
        Ot[h * OTP + rr] = g_heads[((size_t)(m0 + rr) * Jn + j) * Hn + h];
    }
    __syncthreads();

    const int ty   = tid >> 5;          // warp: rows ty*8 .. ty*8+7
    const int lane = tid & 31;          // cols lane*4 .. lane*4+3
    const int rowbase = ty * 8;

    // acc[r][c] packs {row 2r, row 2r+1} for column lane*4+c
    u64 acc[4][4];
    #pragma unroll
    for (int r = 0; r < 4; ++r)
        #pragma unroll
        for (int c = 0; c < 4; ++c) acc[r][c] = 0ull;

    const float* obase = Ot + rowbase;
    #pragma unroll 4
    for (int h = 0; h < Hn; ++h) {
        float4 p = *(const float4*)(P + h * Hn + lane * 4);
        u64 d0 = f2pack(p.x, p.x);
        u64 d1 = f2pack(p.y, p.y);
        u64 d2 = f2pack(p.z, p.z);
        u64 d3 = f2pack(p.w, p.w);
        const float* oc = obase + h * OTP;
        #pragma unroll
        for (int r = 0; r < 4; ++r) {
            u64 ov = lds2(oc + 2 * r);
            acc[r][0] = fma2(ov, d0, acc[r][0]);
            acc[r][1] = fma2(ov, d1, acc[r][1]);
            acc[r][2] = fma2(ov, d2, acc[r][2]);
            acc[r][3] = fma2(ov, d3, acc[r][3]);
        }
    }

    // residual + LayerNorm, two rows (pair) at a time
    const float4 g  = *(const float4*)(gamma + lane * 4);
    const float4 bt = *(const float4*)(beta  + lane * 4);
    #pragma unroll
    for (int r = 0; r < 4; ++r) {
        const int row0 = rowbase + 2 * r;
        const float* xr = x + ((size_t)(m0 + row0) * Jn + j) * Hn + lane * 4;
        float4 xa = *(const float4*)xr;
        float4 xb = *(const float4*)(xr + Jn * Hn);

        float ve0, vo0, ve1, vo1, ve2, vo2, ve3, vo3;
        f2unpack(acc[r][0], ve0, vo0);
        f2unpack(acc[r][1], ve1, vo1);
        f2unpack(acc[r][2], ve2, vo2);
        f2unpack(acc[r][3], ve3, vo3);
        ve0 += xa.x; ve1 += xa.y; ve2 += xa.z; ve3 += xa.w;
        vo0 += xb.x; vo1 += xb.y; vo2 += xb.z; vo3 += xb.w;

        u64 ss = f2pack(ve0 + ve1 + ve2 + ve3, vo0 + vo1 + vo2 + vo3);
        u64 sq = f2pack(fmaf(ve0, ve0, fmaf(ve1, ve1, fmaf(ve2, ve2, ve3 * ve3))),
                        fmaf(vo0, vo0, fmaf(vo1, vo1, fmaf(vo2, vo2, vo3 * vo3))));
        #pragma unroll
        for (int o = 16; o; o >>= 1) {
            u64 s2 = __shfl_xor_sync(0xffffffffu, ss, o);
            u64 q2 = __shfl_xor_sync(0xffffffffu, sq, o);
            float sa, sb2, qa2, qb2, ca, cb, da, db;
            f2unpack(ss, sa, sb2); f2unpack(s2, ca, cb);
            f2unpack(sq, qa2, qb2); f2unpack(q2, da, db);
            ss = f2pack(sa + ca, sb2 + cb);
            sq = f2pack(qa2 + da, qb2 + db);
        }
        float se, so, qe, qo;
        f2unpack(ss, se, so);
        f2unpack(sq, qe, qo);
        float me = se * (1.f / 128.f), mo = so * (1.f / 128.f);
        float re = rsqrtf(qe * (1.f / 128.f) - me * me + LN_EPS);
        float ro = rsqrtf(qo * (1.f / 128.f) - mo * mo + LN_EPS);

        float* orow = out + ((size_t)(m0 + row0) * Jn + j) * Hn + lane * 4;
        float4 oa, ob;
        oa.x = (ve0 - me) * re * g.x + bt.x;
        oa.y = (ve1 - me) * re * g.y + bt.y;
        oa.z = (ve2 - me) * re * g.z + bt.z;
        oa.w = (ve3 - me) * re * g.w + bt.w;
        ob.x = (vo0 - mo) * ro * g.x + bt.x;
        ob.y = (vo1 - mo) * ro * g.y + bt.y;
        ob.z = (vo2 - mo) * ro * g.z + bt.z;
        ob.w = (vo3 - mo) * ro * g.w + bt.w;
        *(float4*)orow = oa;
        *(float4*)(orow + Jn * Hn) = ob;
    }
}

// ---------------------------------------------------------------------------
// Launch
// ---------------------------------------------------------------------------
extern "C" void kernel_launch(void* const* d_in, const int* in_sizes, int n_in,
                              void* d_out, int out_size)
{
    const float* x     = (const float*)d_in[0];
    // d_in[1] = mask (pure causal, handled analytically)
    const float* qm    = (const float*)d_in[2];
    const float* km    = (const float*)d_in[3];
    const float* vm    = (const float*)d_in[4];
    const float* proj  = (const float*)d_in[5];
    const float* gamma = (const float*)d_in[6];
    const float* beta  = (const float*)d_in[7];
    float* out = (float*)d_out;

    const int smem1 = (3 * Sn * HSP + 3 * HSn * WP + 64 * Hn) * (int)sizeof(float); // 168320
    const int smem2 = (Hn * Hn + Hn * OTP) * (int)sizeof(float);                    // 99328

    cudaFuncSetAttribute(attn_kernel, cudaFuncAttributeMaxDynamicSharedMemorySize, smem1);
    cudaFuncSetAttribute(proj_ln_kernel, cudaFuncAttributeMaxDynamicSharedMemorySize, smem2);

    attn_kernel<<<Bn * NHn * Jn, 256, smem1>>>(x, qm, km, vm);
    proj_ln_kernel<<<Jn * (Bn * Sn / 64), 256, smem2>>>(x, proj, gamma, beta, out);
}

// round 12
// speedup vs baseline: 2.6148x; 1.0043x over previous
#include <cuda_runtime.h>
#include <cuda_bf16.h>

// Problem constants
#define Bn   4
#define Sn   512
#define Jn   24
#define Hn   128
#define NHn  8
#define HSn  16
#define HSP  18          // Q/K/V smem row stride (8B aligned)
#define WP   130         // transposed-weight row stride (conflict-free per pd)
#define OTP  66          // transposed-O row stride in kernel 2 (64 rows + pad)
#define LN_EPS 1e-5f

typedef unsigned long long u64;

// Scratch: attention head outputs in (B, S, J, NH*HS) layout
__device__ float g_heads[Bn * Sn * Jn * Hn];

// ---- packed f32x2 helpers ----
__device__ __forceinline__ u64 f2pack(float lo, float hi) {
    u64 r; asm("mov.b64 %0,{%1,%2};" : "=l"(r) : "f"(lo), "f"(hi)); return r;
}
__device__ __forceinline__ void f2unpack(u64 v, float& lo, float& hi) {
    asm("mov.b64 {%0,%1},%2;" : "=f"(lo), "=f"(hi) : "l"(v));
}
__device__ __forceinline__ u64 fma2(u64 a, u64 b, u64 c) {
    u64 d; asm("fma.rn.f32x2 %0,%1,%2,%3;" : "=l"(d) : "l"(a), "l"(b), "l"(c)); return d;
}
__device__ __forceinline__ u64 mul2(u64 a, u64 b) {
    u64 d; asm("mul.rn.f32x2 %0,%1,%2;" : "=l"(d) : "l"(a), "l"(b)); return d;
}
__device__ __forceinline__ float f2sum(u64 v) { float a, b; f2unpack(v, a, b); return a + b; }
__device__ __forceinline__ u64 lds2(const float* p) { return *reinterpret_cast<const u64*>(p); }

// ---------------------------------------------------------------------------
// Kernel 1: per (b, n, j) block — QKV projection + causal attention
//   grid = B*NH*J = 768 blocks, 256 threads
// ---------------------------------------------------------------------------
__global__ void __launch_bounds__(256, 1)
attn_kernel(const float* __restrict__ x,
            const float* __restrict__ qm,
            const float* __restrict__ km,
            const float* __restrict__ vm)
{
    extern __shared__ float sm[];
    float* Q   = sm;                    // Sn * HSP = 9216
    float* K   = Q + Sn * HSP;
    float* V   = K + Sn * HSP;
    float* Wqt = V + Sn * HSP;          // 16 * WP each
    float* Wkt = Wqt + HSn * WP;
    float* Wvt = Wkt + HSn * WP;
    float* Xt  = Wvt + HSn * WP;        // 64 * 128

    const int tid = threadIdx.x;
    const int blk = blockIdx.x;
    const int j = blk % Jn;
    const int n = (blk / Jn) % NHn;
    const int b = blk / (Jn * NHn);

    // --- Phase A: load weights transposed to [pd][h]; fold 0.25 into Wq ---
    const float* qmj = qm + ((n * Jn + j) * Hn) * HSn;
    const float* kmj = km + ((n * Jn + j) * Hn) * HSn;
    const float* vmj = vm + ((n * Jn + j) * Hn) * HSn;
    for (int i = tid; i < Hn * HSn; i += 256) {
        int h = i >> 4, pd_ = i & 15;
        Wqt[pd_ * WP + h] = qmj[i] * 0.25f;   // 1/sqrt(HS)
        Wkt[pd_ * WP + h] = kmj[i];
        Wvt[pd_ * WP + h] = vmj[i];
    }
    __syncthreads();

    // --- Phase B: QKV projection, 8 tiles of 64 rows, 4 rows per thread ---
    const int pr = tid >> 4;     // 0..15
    const int pd = tid & 15;     // 0..15
    const float* wq = Wqt + pd * WP;
    const float* wk = Wkt + pd * WP;
    const float* wv = Wvt + pd * WP;

    for (int t0 = 0; t0 < Sn; t0 += 64) {
        for (int i = tid; i < 64 * 32; i += 256) {
            int rr = i >> 5, c = i & 31;
            ((float4*)Xt)[i] = ((const float4*)(x + (((size_t)b * Sn + (t0 + rr)) * Jn + j) * Hn))[c];
        }
        __syncthreads();

        u64 aq[4] = {0,0,0,0}, ak[4] = {0,0,0,0}, av[4] = {0,0,0,0};
        #pragma unroll 8
        for (int h = 0; h < Hn; h += 2) {
            u64 wqv = lds2(wq + h);
            u64 wkv = lds2(wk + h);
            u64 wvv = lds2(wv + h);
            #pragma unroll
            for (int k = 0; k < 4; ++k) {
                u64 xv = lds2(Xt + (pr + 16 * k) * Hn + h);
                aq[k] = fma2(xv, wqv, aq[k]);
                ak[k] = fma2(xv, wkv, ak[k]);
                av[k] = fma2(xv, wvv, av[k]);
            }
        }
        #pragma unroll
        for (int k = 0; k < 4; ++k) {
            int s = t0 + pr + 16 * k;
            Q[s * HSP + pd] = f2sum(aq[k]);
            K[s * HSP + pd] = f2sum(ak[k]);
            V[s * HSP + pd] = f2sum(av[k]);
        }
        __syncthreads();
    }

    // --- Phase C: causal attention, lane = query, keys broadcast ---
    // warp -> group map balances fma cycles across SMSPs (pairs sum to 7+4? ->
    // SMSP s hosts warps s and s+4 -> groups s and 7-s, equal totals).
    const int warp = tid >> 5;
    const int lane = tid & 31;
    const int g = (warp < 4) ? warp : (11 - warp);   // 0..7
    const int qa = 64 * g + lane;
    const int qb = qa + 32;

    u64 qra[8], qrb[8];
    {
        const float* qpa = Q + qa * HSP;
        const float* qpb = Q + qb * HSP;
        #pragma unroll
        for (int i = 0; i < 8; ++i) {
            qra[i] = lds2(qpa + 2 * i);
            qrb[i] = lds2(qpb + 2 * i);
        }
    }

    u64 oa[8], ob[8];
    #pragma unroll
    for (int i = 0; i < 8; ++i) { oa[i] = 0ull; ob[i] = 0ull; }
    float suma = 0.f, sumb = 0.f;

    const int tend1 = 64 * g + 32;

    for (int t = 0; t < tend1; ++t) {
        const float* kp = K + t * HSP;
        u64 kk[8];
        #pragma unroll
        for (int i = 0; i < 8; ++i) kk[i] = lds2(kp + 2 * i);

        u64 da = mul2(qra[0], kk[0]);
        u64 db = mul2(qrb[0], kk[0]);
        #pragma unroll
        for (int i = 1; i < 8; ++i) {
            da = fma2(qra[i], kk[i], da);
            db = fma2(qrb[i], kk[i], db);
        }
        float ea = __expf(f2sum(da));
        float eb = __expf(f2sum(db));
        if (t > qa) ea = 0.f;            // qb >= tend1-? qb >= 64g+32 > t always
        suma += ea; sumb += eb;

        const float* vp = V + t * HSP;
        u64 ea2 = f2pack(ea, ea), eb2 = f2pack(eb, eb);
        #pragma unroll
        for (int i = 0; i < 8; ++i) {
            u64 vv = lds2(vp + 2 * i);
            oa[i] = fma2(ea2, vv, oa[i]);
            ob[i] = fma2(eb2, vv, ob[i]);
        }
    }
    // tail: only the upper 32 queries are active
    for (int t = tend1; t < tend1 + 32; ++t) {
        const float* kp = K + t * HSP;
        u64 kk[8];
        #pragma unroll
        for (int i = 0; i < 8; ++i) kk[i] = lds2(kp + 2 * i);
        u64 db = mul2(qrb[0], kk[0]);
        #pragma unroll
        for (int i = 1; i < 8; ++i) db = fma2(qrb[i], kk[i], db);
        float eb = __expf(f2sum(db));
        if (t > qb) eb = 0.f;
        sumb += eb;
        const float* vp = V + t * HSP;
        u64 eb2 = f2pack(eb, eb);
        #pragma unroll
        for (int i = 0; i < 8; ++i)
            ob[i] = fma2(eb2, lds2(vp + 2 * i), ob[i]);
    }

    // write: each lane owns rows qa, qb fully (no reductions)
    {
        float inva = 1.f / suma, invb = 1.f / sumb;
        float* pa = g_heads + (((size_t)b * Sn + qa) * Jn + j) * Hn + n * HSn;
        float* pb = g_heads + (((size_t)b * Sn + qb) * Jn + j) * Hn + n * HSn;
        #pragma unroll
        for (int c = 0; c < 4; ++c) {
            float a0, a1, a2, a3;
            f2unpack(oa[2 * c],     a0, a1);
            f2unpack(oa[2 * c + 1], a2, a3);
            ((float4*)pa)[c] = make_float4(a0 * inva, a1 * inva, a2 * inva, a3 * inva);
            float b0, b1, b2, b3;
            f2unpack(ob[2 * c],     b0, b1);
            f2unpack(ob[2 * c + 1], b2, b3);
            ((float4*)pb)[c] = make_float4(b0 * invb, b1 * invb, b2 * invb, b3 * invb);
        }
    }
}

// ---------------------------------------------------------------------------
// Kernel 2: per (j, 64-row tile) — output projection + residual + LayerNorm
//   grid = J * (B*S/64) = 768 blocks, 256 threads, 2 CTAs/SM
// ---------------------------------------------------------------------------
__global__ void __launch_bounds__(256, 2)
proj_ln_kernel(const float* __restrict__ x,
               const float* __restrict__ proj,
               const float* __restrict__ gamma,
               const float* __restrict__ beta,
               float* __restrict__ out)
{
    extern __shared__ float sm2[];
    float* P  = sm2;                 // Hn*Hn = 16384
    float* Ot = P + Hn * Hn;         // Hn * OTP (transposed O: [h][row]), 64 rows

    const int tid  = threadIdx.x;
    const int j    = blockIdx.x >> 5;
    const int tile = blockIdx.x & 31;
    const int m0   = tile * 64;

    const float* Pj = proj + j * Hn * Hn;
    for (int i = tid; i < Hn * Hn / 4; i += 256)
        ((float4*)P)[i] = ((const float4*)Pj)[i];
    for (int i = tid; i < 64 * Hn; i += 256) {
        int rr = i >> 7, h = i & 127;
        Ot[h * OTP + rr] = g_heads[((size_t)(m0 + rr) * Jn + j) * Hn + h];
    }
    __syncthreads();

    const int ty   = tid >> 5;          // warp: rows ty*8 .. ty*8+7
    const int lane = tid & 31;          // cols lane*4 .. lane*4+3
    const int rowbase = ty * 8;

    // acc[r][c] packs {row 2r, row 2r+1} for column lane*4+c
    u64 acc[4][4];
    #pragma unroll
    for (int r = 0; r < 4; ++r)
        #pragma unroll
        for (int c = 0; c < 4; ++c) acc[r][c] = 0ull;

    const float* obase = Ot + rowbase;
    #pragma unroll 4
    for (int h = 0; h < Hn; ++h) {
        float4 p = *(const float4*)(P + h * Hn + lane * 4);
        u64 d0 = f2pack(p.x, p.x);
        u64 d1 = f2pack(p.y, p.y);
        u64 d2 = f2pack(p.z, p.z);
        u64 d3 = f2pack(p.w, p.w);
        const float* oc = obase + h * OTP;
        #pragma unroll
        for (int r = 0; r < 4; ++r) {
            u64 ov = lds2(oc + 2 * r);
            acc[r][0] = fma2(ov, d0, acc[r][0]);
            acc[r][1] = fma2(ov, d1, acc[r][1]);
            acc[r][2] = fma2(ov, d2, acc[r][2]);
            acc[r][3] = fma2(ov, d3, acc[r][3]);
        }
    }

    // residual + LayerNorm, two rows (pair) at a time
    const float4 g  = *(const float4*)(gamma + lane * 4);
    const float4 bt = *(const float4*)(beta  + lane * 4);
    #pragma unroll
    for (int r = 0; r < 4; ++r) {
        const int row0 = rowbase + 2 * r;
        const float* xr = x + ((size_t)(m0 + row0) * Jn + j) * Hn + lane * 4;
        float4 xa = *(const float4*)xr;
        float4 xb = *(const float4*)(xr + Jn * Hn);

        float ve0, vo0, ve1, vo1, ve2, vo2, ve3, vo3;
        f2unpack(acc[r][0], ve0, vo0);
        f2unpack(acc[r][1], ve1, vo1);
        f2unpack(acc[r][2], ve2, vo2);
        f2unpack(acc[r][3], ve3, vo3);
        ve0 += xa.x; ve1 += xa.y; ve2 += xa.z; ve3 += xa.w;
        vo0 += xb.x; vo1 += xb.y; vo2 += xb.z; vo3 += xb.w;

        u64 ss = f2pack(ve0 + ve1 + ve2 + ve3, vo0 + vo1 + vo2 + vo3);
        u64 sq = f2pack(fmaf(ve0, ve0, fmaf(ve1, ve1, fmaf(ve2, ve2, ve3 * ve3))),
                        fmaf(vo0, vo0, fmaf(vo1, vo1, fmaf(vo2, vo2, vo3 * vo3))));
        #pragma unroll
        for (int o = 16; o; o >>= 1) {
            u64 s2 = __shfl_xor_sync(0xffffffffu, ss, o);
            u64 q2 = __shfl_xor_sync(0xffffffffu, sq, o);
            float sa, sb2, qa2, qb2, ca, cb, da, db;
            f2unpack(ss, sa, sb2); f2unpack(s2, ca, cb);
            f2unpack(sq, qa2, qb2); f2unpack(q2, da, db);
            ss = f2pack(sa + ca, sb2 + cb);
            sq = f2pack(qa2 + da, qb2 + db);
        }
        float se, so, qe, qo;
        f2unpack(ss, se, so);
        f2unpack(sq, qe, qo);
        float me = se * (1.f / 128.f), mo = so * (1.f / 128.f);
        float re = rsqrtf(qe * (1.f / 128.f) - me * me + LN_EPS);
        float ro = rsqrtf(qo * (1.f / 128.f) - mo * mo + LN_EPS);

        float* orow = out + ((size_t)(m0 + row0) * Jn + j) * Hn + lane * 4;
        float4 oa, ob;
        oa.x = (ve0 - me) * re * g.x + bt.x;
        oa.y = (ve1 - me) * re * g.y + bt.y;
        oa.z = (ve2 - me) * re * g.z + bt.z;
        oa.w = (ve3 - me) * re * g.w + bt.w;
        ob.x = (vo0 - mo) * ro * g.x + bt.x;
        ob.y = (vo1 - mo) * ro * g.y + bt.y;
        ob.z = (vo2 - mo) * ro * g.z + bt.z;
        ob.w = (vo3 - mo) * ro * g.w + bt.w;
        *(float4*)orow = oa;
        *(float4*)(orow + Jn * Hn) = ob;
    }
}

// ---------------------------------------------------------------------------
// Launch
// ---------------------------------------------------------------------------
extern "C" void kernel_launch(void* const* d_in, const int* in_sizes, int n_in,
                              void* d_out, int out_size)
{
    const float* x     = (const float*)d_in[0];
    // d_in[1] = mask (pure causal, handled analytically)
    const float* qm    = (const float*)d_in[2];
    const float* km    = (const float*)d_in[3];
    const float* vm    = (const float*)d_in[4];
    const float* proj  = (const float*)d_in[5];
    const float* gamma = (const float*)d_in[6];
    const float* beta  = (const float*)d_in[7];
    float* out = (float*)d_out;

    const int smem1 = (3 * Sn * HSP + 3 * HSn * WP + 64 * Hn) * (int)sizeof(float); // 168320
    const int smem2 = (Hn * Hn + Hn * OTP) * (int)sizeof(float);                    // 99328

    cudaFuncSetAttribute(attn_kernel, cudaFuncAttributeMaxDynamicSharedMemorySize, smem1);
    cudaFuncSetAttribute(proj_ln_kernel, cudaFuncAttributeMaxDynamicSharedMemorySize, smem2);

    attn_kernel<<<Bn * NHn * Jn, 256, smem1>>>(x, qm, km, vm);
    proj_ln_kernel<<<Jn * (Bn * Sn / 64), 256, smem2>>>(x, proj, gamma, beta, out);
}